// round 16
// baseline (speedup 1.0000x reference)
#include <cuda_runtime.h>
#include <cuda_fp16.h>
#include <cstddef>

// ---------------------------------------------------------------------------
// Compile-time Gaussian weights (passed BY VALUE so they fold to FFMA-imm)
// ---------------------------------------------------------------------------
constexpr double cexp_pos(double x) {
    double term = 1.0, sum = 1.0;
    for (int i = 1; i < 200; ++i) {
        term *= x / (double)i;
        if (term < 1e-250) break;
        sum += term;
    }
    return sum;
}

template <int KS>
struct Wt { float w[KS]; };

template <int KS>
constexpr Wt<KS> make_w(double sigma) {
    Wt<KS> W{};
    double wd[KS]{};
    double s = 0.0;
    for (int i = 0; i < KS; ++i) {
        double d = (double)(i - KS / 2);
        double e = 1.0 / cexp_pos(d * d / (2.0 * sigma * sigma));
        wd[i] = e;
        s += e;
    }
    for (int i = 0; i < KS; ++i) W.w[i] = (float)(wd[i] / s);
    return W;
}

constexpr Wt<7>   CW0 = make_w<7>(0.6);
constexpr Wt<9>   CW1 = make_w<9>(1.2);
constexpr Wt<17>  CW2 = make_w<17>(2.4);
constexpr Wt<31>  CW3 = make_w<31>(4.8);
constexpr Wt<59>  CW4 = make_w<59>(9.6);
constexpr Wt<117> CW5 = make_w<117>(19.2);

constexpr int H = 512, W = 512;
constexpr int HW = H * W;
constexpr int NROWS = 8 * 3 * H;        // 12288
constexpr int PMAX = 58;

// Padded scratch planes: 628 rows per 512-row image plane, vertical reflect
// materialized by hpass. fp16, 6 sigmas x 24 planes x 628 x 512 = 92.6 MB.
constexpr int PLH = H + 2 * PMAX;                 // 628
constexpr size_t PL  = (size_t)PLH * W;           // per-plane halfs
constexpr size_t SIG = 24 * PL;                   // per-sigma halfs

__device__ __align__(16) __half g_scratch[6 * SIG];

// ---------------------------------------------------------------------------
// cp.async helpers
// ---------------------------------------------------------------------------
__device__ __forceinline__ void cp_async16(unsigned daddr, const void* gsrc) {
    asm volatile("cp.async.cg.shared.global [%0], [%1], 16;\n"
                 :: "r"(daddr), "l"(gsrc) : "memory");
}
__device__ __forceinline__ void cp_commit() {
    asm volatile("cp.async.commit_group;\n" ::: "memory");
}
template <int N>
__device__ __forceinline__ void cp_wait() {
    asm volatile("cp.async.wait_group %0;\n" :: "n"(N) : "memory");
}

// ---------------------------------------------------------------------------
// Kernel A: horizontal pass — WARP-PRIVATE segments, no CTA barrier (round-15
// winner). Warp w owns row (blk*4 + w/2), col half (w&1)*256. Writes each
// h-blurred row to its padded-plane slot PLUS reflected halo slots.
// ---------------------------------------------------------------------------
constexpr int SEGW = 424;   // 372 valid -> padded max 417, round up

template <int KS>
__device__ __forceinline__ void hconv(const Wt<KS> Wc,
                                      const float* __restrict__ sr,
                                      int lane, __half* __restrict__ planecol,
                                      int pr0, int e1, int e2) {
    constexpr int P  = KS / 2;
    constexpr int S0 = PMAX - P;
    constexpr int Q  = S0 >> 3;
    constexpr int R  = S0 & 7;
    const int base = 9 * (lane + Q);

    float win[8], acc[8];
#pragma unroll
    for (int i = 0; i < 7; ++i)
        win[i] = sr[base + (R + i) + ((R + i) >> 3)];
#pragma unroll
    for (int t = 0; t < 8; ++t) acc[t] = 0.f;
#pragma unroll
    for (int k = 0; k < KS; ++k) {
        const int j = k + 7;
        win[j & 7] = sr[base + (R + j) + ((R + j) >> 3)];
#pragma unroll
        for (int t = 0; t < 8; ++t)
            acc[t] += Wc.w[k] * win[(k + t) & 7];
    }
    __half2 hh[4];
#pragma unroll
    for (int q = 0; q < 4; ++q)
        hh[q] = __floats2half2_rn(acc[2 * q], acc[2 * q + 1]);
    const float4 v = *reinterpret_cast<const float4*>(hh);
    *reinterpret_cast<float4*>(planecol + (size_t)pr0 * W + lane * 8) = v;
    if (e1 >= 0)
        *reinterpret_cast<float4*>(planecol + (size_t)e1 * W + lane * 8) = v;
    if (e2 >= 0)
        *reinterpret_cast<float4*>(planecol + (size_t)e2 * W + lane * 8) = v;
}

__global__ __launch_bounds__(256) void hpass_kernel(const float* __restrict__ img) {
    __shared__ float sr[8][SEGW];
    const int wid  = threadIdx.x >> 5;        // 0..7
    const int lane = threadIdx.x & 31;
    const int row  = blockIdx.x * 4 + (wid >> 1);
    const int cbase = (wid & 1) * 256;        // col half

    const int bc = row >> 9;                  // image plane (b*3+ch)
    const int r  = row & 511;                 // row within plane

    const float* rp = img + (size_t)row * W;
    float* seg = sr[wid];
#pragma unroll
    for (int x = lane; x < 372; x += 32) {
        int gx = cbase + x - PMAX;
        gx = gx < 0 ? -gx : (gx > W - 1 ? 2 * W - 2 - gx : gx);
        seg[x + (x >> 3)] = rp[gx];
    }
    __syncwarp();

    // padded-plane row slots: main + reflected halo copies
    const int pr0 = PMAX + r;
    const int e1  = (r >= 1 && r <= PMAX) ? (PMAX - r) : -1;          // top
    const int e2  = (r >= 453 && r <= 510) ? (1080 - r) : -1;         // bottom

    __half* pbase = g_scratch + (size_t)bc * PL + cbase;
    hconv<7>(CW0, seg, lane, pbase + 0 * SIG, pr0, e1, e2);
    hconv<9>(CW1, seg, lane, pbase + 1 * SIG, pr0, e1, e2);
    hconv<17>(CW2, seg, lane, pbase + 2 * SIG, pr0, e1, e2);
    hconv<31>(CW3, seg, lane, pbase + 3 * SIG, pr0, e1, e2);
    hconv<59>(CW4, seg, lane, pbase + 4 * SIG, pr0, e1, e2);
    hconv<117>(CW5, seg, lane, pbase + 5 * SIG, pr0, e1, e2);

#if defined(__CUDA_ARCH__) && (__CUDA_ARCH__ >= 900)
    cudaTriggerProgrammaticLaunchCompletion();
#endif
}

// ---------------------------------------------------------------------------
// Kernel B: vertical pass + DoG, double-buffered, DESCENDING sigma order,
// fp16 smem tiles (round-12 core). Padded scratch => tile loads are pure
// contiguous box reads (no reflect/bounds ALU).
// Slot A (180 rows) sigma 5,3,1 ; slot B (122 rows) sigma 4,2,0.
// smem = 302 rows * 64 B = 19328 B.
// ---------------------------------------------------------------------------
constexpr int VSMEM_BYTES = 302 * 32 * 2;    // 19328
constexpr int BUFA = 0;                       // half-index
constexpr int BUFB = 180 * 32;

template <int KS, int OFF>
__device__ __forceinline__ void load_tile_async(unsigned smb,
                                                const __half* __restrict__ src,
                                                int tid) {
    constexpr int NR = 64 + KS - 1;
    const unsigned base = smb + (unsigned)OFF * 2u;
    const int c8 = (tid & 3) * 8;            // half offset of this thread's 16B
#pragma unroll
    for (int m = tid >> 2; m < NR; m += 64)
        cp_async16(base + (unsigned)(m * 32 + c8) * 2u,
                   src + (size_t)m * W + c8);
    cp_commit();
}

template <int KS>
__device__ __forceinline__ void vconv(const Wt<KS> Wc,
                                      const __half* __restrict__ smh,
                                      int g, int lane, float acc[8]) {
    const int base = g * 8 * 32 + lane;
    float win[8];
#pragma unroll
    for (int i = 0; i < 7; ++i) win[i] = __half2float(smh[base + i * 32]);
#pragma unroll
    for (int t = 0; t < 8; ++t) acc[t] = 0.f;
#pragma unroll
    for (int k = 0; k < KS; ++k) {
        win[(k + 7) & 7] = __half2float(smh[base + (k + 7) * 32]);
#pragma unroll
        for (int t = 0; t < 8; ++t)
            acc[t] += Wc.w[k] * win[(k + t) & 7];
    }
}

// band_{s+1} = prev - cur (streaming store) ; then prev <- cur
__device__ __forceinline__ void store_desc(float* __restrict__ p,
                                           const float cur[8], float prev[8]) {
#pragma unroll
    for (int t = 0; t < 8; ++t) {
        __stcs(p + (size_t)t * W, prev[t] - cur[t]);
        prev[t] = cur[t];
    }
}

__global__ __launch_bounds__(256) void vpass_kernel(const float* __restrict__ img,
                                                    float* __restrict__ out) {
    extern __shared__ __half smh[];
    const int tid  = threadIdx.x;
    const int lane = tid & 31;
    const int g    = tid >> 5;
    const int c0   = blockIdx.x * 32;
    const int R0   = blockIdx.y * 64;
    const int bc   = blockIdx.z;
    const int b    = bc / 3;
    const int ch   = bc - b * 3;
    const int rbase = R0 + g * 8;

    // img values for band0 — independent of hpass, issue BEFORE grid-dep sync
    const float* imgp = img + (size_t)bc * HW + c0 + lane;
    float imgv[8];
#pragma unroll
    for (int t = 0; t < 8; ++t) imgv[t] = imgp[(size_t)(rbase + t) * W];

#if defined(__CUDA_ARCH__) && (__CUDA_ARCH__ >= 900)
    cudaGridDependencySynchronize();
#endif

    // padded-plane column base; tile for sigma s starts at padded row
    // R0 + PMAX - P  (always in range by construction)
    const __half* pbase = g_scratch + (size_t)bc * PL + c0;
    const unsigned smb = (unsigned)__cvta_generic_to_shared(smh);

    load_tile_async<117, BUFA>(smb, pbase + 5 * SIG + (size_t)(R0 + PMAX - 58) * W, tid);
    load_tile_async<59,  BUFB>(smb, pbase + 4 * SIG + (size_t)(R0 + PMAX - 29) * W, tid);

    float prev[8], cur[8];
    float* outp = out + ((size_t)b * 21 + ch) * HW + (size_t)rbase * W + c0 + lane;

    // ---- sigma5 (A): band6 = G5
    cp_wait<1>(); __syncthreads();
    vconv<117>(CW5, smh + BUFA, g, lane, cur);
#pragma unroll
    for (int t = 0; t < 8; ++t) {
        __stcs(outp + 6 * (size_t)(3 * HW) + (size_t)t * W, cur[t]);
        prev[t] = cur[t];
    }
    __syncthreads();
    load_tile_async<31, BUFA>(smb, pbase + 3 * SIG + (size_t)(R0 + PMAX - 15) * W, tid);

    // ---- sigma4 (B): band5 = G5 - G4
    cp_wait<1>(); __syncthreads();
    vconv<59>(CW4, smh + BUFB, g, lane, cur);
    store_desc(outp + 5 * (size_t)(3 * HW), cur, prev);
    __syncthreads();
    load_tile_async<17, BUFB>(smb, pbase + 2 * SIG + (size_t)(R0 + PMAX - 8) * W, tid);

    // ---- sigma3 (A): band4 = G4 - G3
    cp_wait<1>(); __syncthreads();
    vconv<31>(CW3, smh + BUFA, g, lane, cur);
    store_desc(outp + 4 * (size_t)(3 * HW), cur, prev);
    __syncthreads();
    load_tile_async<9, BUFA>(smb, pbase + 1 * SIG + (size_t)(R0 + PMAX - 4) * W, tid);

    // ---- sigma2 (B): band3 = G3 - G2
    cp_wait<1>(); __syncthreads();
    vconv<17>(CW2, smh + BUFB, g, lane, cur);
    store_desc(outp + 3 * (size_t)(3 * HW), cur, prev);
    __syncthreads();
    load_tile_async<7, BUFB>(smb, pbase + 0 * SIG + (size_t)(R0 + PMAX - 3) * W, tid);

    // ---- sigma1 (A): band2 = G2 - G1
    cp_wait<1>(); __syncthreads();
    vconv<9>(CW1, smh + BUFA, g, lane, cur);
    store_desc(outp + 2 * (size_t)(3 * HW), cur, prev);

    // ---- sigma0 (B): band1 = G1 - G0
    cp_wait<0>(); __syncthreads();
    vconv<7>(CW0, smh + BUFB, g, lane, cur);
    store_desc(outp + 1 * (size_t)(3 * HW), cur, prev);

    // band0 = G0 - img (prev now holds G0)
#pragma unroll
    for (int t = 0; t < 8; ++t)
        __stcs(outp + (size_t)t * W, prev[t] - imgv[t]);
}

// ---------------------------------------------------------------------------
extern "C" void kernel_launch(void* const* d_in, const int* in_sizes, int n_in,
                              void* d_out, int out_size) {
    const float* img = (const float*)d_in[0];
    float* out = (float*)d_out;

    cudaFuncSetAttribute(vpass_kernel,
                         cudaFuncAttributeMaxDynamicSharedMemorySize,
                         VSMEM_BYTES);

    hpass_kernel<<<NROWS / 4, 256>>>(img);

    // vpass with programmatic dependent launch (overlap hpass tail);
    // fall back to a plain dependent launch if PDL is unavailable.
    cudaLaunchAttribute attrs[1];
    attrs[0].id = cudaLaunchAttributeProgrammaticStreamSerialization;
    attrs[0].val.programmaticStreamSerializationAllowed = 1;

    cudaLaunchConfig_t cfg = {};
    cfg.gridDim = dim3(W / 32, H / 64, 8 * 3);
    cfg.blockDim = dim3(256, 1, 1);
    cfg.dynamicSmemBytes = VSMEM_BYTES;
    cfg.stream = 0;
    cfg.attrs = attrs;
    cfg.numAttrs = 1;

    cudaError_t e = cudaLaunchKernelEx(&cfg, vpass_kernel, img, out);
    if (e != cudaSuccess) {
        (void)cudaGetLastError();   // clear
        vpass_kernel<<<dim3(W / 32, H / 64, 8 * 3), 256, VSMEM_BYTES>>>(img, out);
    }
}

// round 17
// speedup vs baseline: 1.5962x; 1.5962x over previous
#include <cuda_runtime.h>
#include <cuda_fp16.h>
#include <cstddef>

// ---------------------------------------------------------------------------
// Compile-time Gaussian weights (passed BY VALUE so they fold to FFMA-imm)
// ---------------------------------------------------------------------------
constexpr double cexp_pos(double x) {
    double term = 1.0, sum = 1.0;
    for (int i = 1; i < 200; ++i) {
        term *= x / (double)i;
        if (term < 1e-250) break;
        sum += term;
    }
    return sum;
}

template <int KS>
struct Wt { float w[KS]; };

template <int KS>
constexpr Wt<KS> make_w(double sigma) {
    Wt<KS> W{};
    double wd[KS]{};
    double s = 0.0;
    for (int i = 0; i < KS; ++i) {
        double d = (double)(i - KS / 2);
        double e = 1.0 / cexp_pos(d * d / (2.0 * sigma * sigma));
        wd[i] = e;
        s += e;
    }
    for (int i = 0; i < KS; ++i) W.w[i] = (float)(wd[i] / s);
    return W;
}

constexpr Wt<7>   CW0 = make_w<7>(0.6);
constexpr Wt<9>   CW1 = make_w<9>(1.2);
constexpr Wt<17>  CW2 = make_w<17>(2.4);
constexpr Wt<31>  CW3 = make_w<31>(4.8);
constexpr Wt<59>  CW4 = make_w<59>(9.6);
constexpr Wt<117> CW5 = make_w<117>(19.2);

constexpr int H = 512, W = 512;
constexpr int HW = H * W;
constexpr int NROWS = 8 * 3 * H;        // 12288
constexpr int PMAX = 58;

// Padded scratch planes: 628 rows per 512-row image plane, vertical reflect
// materialized by hpass. fp16, 6 sigmas x 24 planes x 628 x 512 = 92.6 MB.
constexpr int PLH = H + 2 * PMAX;                 // 628
constexpr size_t PL  = (size_t)PLH * W;           // per-plane halfs
constexpr size_t SIG = 24 * PL;                   // per-sigma halfs

__device__ __align__(16) __half g_scratch[6 * SIG];

// ---------------------------------------------------------------------------
// cp.async helpers
// ---------------------------------------------------------------------------
__device__ __forceinline__ void cp_async16(unsigned daddr, const void* gsrc) {
    asm volatile("cp.async.cg.shared.global [%0], [%1], 16;\n"
                 :: "r"(daddr), "l"(gsrc) : "memory");
}
__device__ __forceinline__ void cp_commit() {
    asm volatile("cp.async.commit_group;\n" ::: "memory");
}
template <int N>
__device__ __forceinline__ void cp_wait() {
    asm volatile("cp.async.wait_group %0;\n" :: "n"(N) : "memory");
}

// ---------------------------------------------------------------------------
// Kernel A: horizontal pass — WARP-PRIVATE segments, no CTA barrier (round-15
// winner). Warp w owns row (blk*4 + w/2), col half (w&1)*256. Writes each
// h-blurred row to its padded-plane slot PLUS reflected halo slots.
// ---------------------------------------------------------------------------
constexpr int SEGW = 424;   // 372 valid -> padded max 417, round up

template <int KS>
__device__ __forceinline__ void hconv(const Wt<KS> Wc,
                                      const float* __restrict__ sr,
                                      int lane, __half* __restrict__ planecol,
                                      int pr0, int e1, int e2) {
    constexpr int P  = KS / 2;
    constexpr int S0 = PMAX - P;
    constexpr int Q  = S0 >> 3;
    constexpr int R  = S0 & 7;
    const int base = 9 * (lane + Q);

    float win[8], acc[8];
#pragma unroll
    for (int i = 0; i < 7; ++i)
        win[i] = sr[base + (R + i) + ((R + i) >> 3)];
#pragma unroll
    for (int t = 0; t < 8; ++t) acc[t] = 0.f;
#pragma unroll
    for (int k = 0; k < KS; ++k) {
        const int j = k + 7;
        win[j & 7] = sr[base + (R + j) + ((R + j) >> 3)];
#pragma unroll
        for (int t = 0; t < 8; ++t)
            acc[t] += Wc.w[k] * win[(k + t) & 7];
    }
    __half2 hh[4];
#pragma unroll
    for (int q = 0; q < 4; ++q)
        hh[q] = __floats2half2_rn(acc[2 * q], acc[2 * q + 1]);
    const float4 v = *reinterpret_cast<const float4*>(hh);
    *reinterpret_cast<float4*>(planecol + (size_t)pr0 * W + lane * 8) = v;
    if (e1 >= 0)
        *reinterpret_cast<float4*>(planecol + (size_t)e1 * W + lane * 8) = v;
    if (e2 >= 0)
        *reinterpret_cast<float4*>(planecol + (size_t)e2 * W + lane * 8) = v;
}

__global__ __launch_bounds__(256) void hpass_kernel(const float* __restrict__ img) {
    __shared__ float sr[8][SEGW];
    const int wid  = threadIdx.x >> 5;        // 0..7
    const int lane = threadIdx.x & 31;
    const int row  = blockIdx.x * 4 + (wid >> 1);
    const int cbase = (wid & 1) * 256;        // col half

    const int bc = row >> 9;                  // image plane (b*3+ch)
    const int r  = row & 511;                 // row within plane

    const float* rp = img + (size_t)row * W;
    float* seg = sr[wid];
#pragma unroll
    for (int x = lane; x < 372; x += 32) {
        int gx = cbase + x - PMAX;
        gx = gx < 0 ? -gx : (gx > W - 1 ? 2 * W - 2 - gx : gx);
        seg[x + (x >> 3)] = rp[gx];
    }
    __syncwarp();

    // padded-plane row slots: main + reflected halo copies
    const int pr0 = PMAX + r;
    const int e1  = (r >= 1 && r <= PMAX) ? (PMAX - r) : -1;          // top
    const int e2  = (r >= 453 && r <= 510) ? (1080 - r) : -1;         // bottom

    __half* pbase = g_scratch + (size_t)bc * PL + cbase;
    hconv<7>(CW0, seg, lane, pbase + 0 * SIG, pr0, e1, e2);
    hconv<9>(CW1, seg, lane, pbase + 1 * SIG, pr0, e1, e2);
    hconv<17>(CW2, seg, lane, pbase + 2 * SIG, pr0, e1, e2);
    hconv<31>(CW3, seg, lane, pbase + 3 * SIG, pr0, e1, e2);
    hconv<59>(CW4, seg, lane, pbase + 4 * SIG, pr0, e1, e2);
    hconv<117>(CW5, seg, lane, pbase + 5 * SIG, pr0, e1, e2);
}

// ---------------------------------------------------------------------------
// Kernel B: vertical pass + DoG, double-buffered, DESCENDING sigma order,
// fp16 smem tiles. Padded scratch => tile loads are pure contiguous box
// reads (no reflect/bounds ALU). Slot A (180 rows) sigma 5,3,1 ; slot B
// (122 rows) sigma 4,2,0. smem = 302 rows * 64 B = 19328 B.
// ---------------------------------------------------------------------------
constexpr int VSMEM_BYTES = 302 * 32 * 2;    // 19328
constexpr int BUFA = 0;                       // half-index
constexpr int BUFB = 180 * 32;

template <int KS, int OFF>
__device__ __forceinline__ void load_tile_async(unsigned smb,
                                                const __half* __restrict__ src,
                                                int tid) {
    constexpr int NR = 64 + KS - 1;
    const unsigned base = smb + (unsigned)OFF * 2u;
    const int c8 = (tid & 3) * 8;            // half offset of this thread's 16B
#pragma unroll
    for (int m = tid >> 2; m < NR; m += 64)
        cp_async16(base + (unsigned)(m * 32 + c8) * 2u,
                   src + (size_t)m * W + c8);
    cp_commit();
}

template <int KS>
__device__ __forceinline__ void vconv(const Wt<KS> Wc,
                                      const __half* __restrict__ smh,
                                      int g, int lane, float acc[8]) {
    const int base = g * 8 * 32 + lane;
    float win[8];
#pragma unroll
    for (int i = 0; i < 7; ++i) win[i] = __half2float(smh[base + i * 32]);
#pragma unroll
    for (int t = 0; t < 8; ++t) acc[t] = 0.f;
#pragma unroll
    for (int k = 0; k < KS; ++k) {
        win[(k + 7) & 7] = __half2float(smh[base + (k + 7) * 32]);
#pragma unroll
        for (int t = 0; t < 8; ++t)
            acc[t] += Wc.w[k] * win[(k + t) & 7];
    }
}

// band_{s+1} = prev - cur (streaming store) ; then prev <- cur
__device__ __forceinline__ void store_desc(float* __restrict__ p,
                                           const float cur[8], float prev[8]) {
#pragma unroll
    for (int t = 0; t < 8; ++t) {
        __stcs(p + (size_t)t * W, prev[t] - cur[t]);
        prev[t] = cur[t];
    }
}

__global__ __launch_bounds__(256) void vpass_kernel(const float* __restrict__ img,
                                                    float* __restrict__ out) {
    extern __shared__ __half smh[];
    const int tid  = threadIdx.x;
    const int lane = tid & 31;
    const int g    = tid >> 5;
    const int c0   = blockIdx.x * 32;
    const int R0   = blockIdx.y * 64;
    const int bc   = blockIdx.z;
    const int b    = bc / 3;
    const int ch   = bc - b * 3;
    const int rbase = R0 + g * 8;

    // padded-plane column base; tile for sigma s starts at padded row
    // R0 + PMAX - P  (always in range by construction)
    const __half* pbase = g_scratch + (size_t)bc * PL + c0;
    const unsigned smb = (unsigned)__cvta_generic_to_shared(smh);

    load_tile_async<117, BUFA>(smb, pbase + 5 * SIG + (size_t)(R0 + PMAX - 58) * W, tid);
    load_tile_async<59,  BUFB>(smb, pbase + 4 * SIG + (size_t)(R0 + PMAX - 29) * W, tid);

    // img values for band0 (held in regs; LDG overlaps the cp.asyncs)
    const float* imgp = img + (size_t)bc * HW + c0 + lane;
    float imgv[8];
#pragma unroll
    for (int t = 0; t < 8; ++t) imgv[t] = imgp[(size_t)(rbase + t) * W];

    float prev[8], cur[8];
    float* outp = out + ((size_t)b * 21 + ch) * HW + (size_t)rbase * W + c0 + lane;

    // ---- sigma5 (A): band6 = G5
    cp_wait<1>(); __syncthreads();
    vconv<117>(CW5, smh + BUFA, g, lane, cur);
#pragma unroll
    for (int t = 0; t < 8; ++t) {
        __stcs(outp + 6 * (size_t)(3 * HW) + (size_t)t * W, cur[t]);
        prev[t] = cur[t];
    }
    __syncthreads();
    load_tile_async<31, BUFA>(smb, pbase + 3 * SIG + (size_t)(R0 + PMAX - 15) * W, tid);

    // ---- sigma4 (B): band5 = G5 - G4
    cp_wait<1>(); __syncthreads();
    vconv<59>(CW4, smh + BUFB, g, lane, cur);
    store_desc(outp + 5 * (size_t)(3 * HW), cur, prev);
    __syncthreads();
    load_tile_async<17, BUFB>(smb, pbase + 2 * SIG + (size_t)(R0 + PMAX - 8) * W, tid);

    // ---- sigma3 (A): band4 = G4 - G3
    cp_wait<1>(); __syncthreads();
    vconv<31>(CW3, smh + BUFA, g, lane, cur);
    store_desc(outp + 4 * (size_t)(3 * HW), cur, prev);
    __syncthreads();
    load_tile_async<9, BUFA>(smb, pbase + 1 * SIG + (size_t)(R0 + PMAX - 4) * W, tid);

    // ---- sigma2 (B): band3 = G3 - G2
    cp_wait<1>(); __syncthreads();
    vconv<17>(CW2, smh + BUFB, g, lane, cur);
    store_desc(outp + 3 * (size_t)(3 * HW), cur, prev);
    __syncthreads();
    load_tile_async<7, BUFB>(smb, pbase + 0 * SIG + (size_t)(R0 + PMAX - 3) * W, tid);

    // ---- sigma1 (A): band2 = G2 - G1
    cp_wait<1>(); __syncthreads();
    vconv<9>(CW1, smh + BUFA, g, lane, cur);
    store_desc(outp + 2 * (size_t)(3 * HW), cur, prev);

    // ---- sigma0 (B): band1 = G1 - G0
    cp_wait<0>(); __syncthreads();
    vconv<7>(CW0, smh + BUFB, g, lane, cur);
    store_desc(outp + 1 * (size_t)(3 * HW), cur, prev);

    // band0 = G0 - img (prev now holds G0)
#pragma unroll
    for (int t = 0; t < 8; ++t)
        __stcs(outp + (size_t)t * W, prev[t] - imgv[t]);
}

// ---------------------------------------------------------------------------
extern "C" void kernel_launch(void* const* d_in, const int* in_sizes, int n_in,
                              void* d_out, int out_size) {
    const float* img = (const float*)d_in[0];
    float* out = (float*)d_out;

    cudaFuncSetAttribute(vpass_kernel,
                         cudaFuncAttributeMaxDynamicSharedMemorySize,
                         VSMEM_BYTES);

    hpass_kernel<<<NROWS / 4, 256>>>(img);
    vpass_kernel<<<dim3(W / 32, H / 64, 8 * 3), 256, VSMEM_BYTES>>>(img, out);
}